// round 7
// baseline (speedup 1.0000x reference)
#include <cuda_runtime.h>
#include <cuda_bf16.h>
#include <math.h>
#include <stdint.h>

// Problem constants: bs=2, seq=2048, d_model=512, heads=8, d_k=64
#define DM     512
#define HEADS  8
#define DK     64
#define SEQ    2048
#define BS     2
#define TOK    (SEQ*BS)     // 4096
#define VCHUNK 64

// ---------------- scratch (device globals; no allocations allowed) -------------
__device__ float g_Q[TOK * DM];
__device__ float g_K[TOK * DM];
__device__ float g_V[TOK * DM];
__device__ float g_ctx[TOK * DM];
__device__ __nv_bfloat16 g_ahi[3 * TOK * DM];
__device__ __nv_bfloat16 g_alo[3 * TOK * DM];
__device__ __nv_bfloat16 g_wthi[4][DM * DM];   // transposed weights [N,K], hi part
__device__ __nv_bfloat16 g_wtlo[4][DM * DM];   // lo part
__device__ float g_vpart[VCHUNK][BS * DM];
__device__ float g_vsum[BS * DM];

struct WIn  { const float* W[4]; };
struct CIn  { const float* x[3]; };
struct GOut { float* C[3]; const float* bias[3]; };

// ================= helpers ======================================================
__device__ __forceinline__ uint32_t smem_u32(const void* p) {
    uint32_t a;
    asm("{ .reg .u64 t; cvta.to.shared.u64 t, %1; cvt.u32.u64 %0, t; }" : "=r"(a) : "l"(p));
    return a;
}
__device__ __forceinline__ uint32_t sw128(uint32_t o) { return o ^ ((o >> 3) & 0x70); }

__device__ __forceinline__ void cp16(uint32_t dst, const void* src) {
    asm volatile("cp.async.cg.shared.global [%0], [%1], 16;" :: "r"(dst), "l"(src));
}
__device__ __forceinline__ void ldsm4(uint32_t* r, uint32_t addr) {
    asm volatile("ldmatrix.sync.aligned.m8n8.x4.shared.b16 {%0,%1,%2,%3}, [%4];"
        : "=r"(r[0]), "=r"(r[1]), "=r"(r[2]), "=r"(r[3]) : "r"(addr));
}
__device__ __forceinline__ void mma16816(float* c, const uint32_t* a, uint32_t b0, uint32_t b1) {
    asm volatile("mma.sync.aligned.m16n8k16.row.col.f32.bf16.bf16.f32 "
        "{%0,%1,%2,%3}, {%4,%5,%6,%7}, {%8,%9}, {%0,%1,%2,%3};"
        : "+f"(c[0]), "+f"(c[1]), "+f"(c[2]), "+f"(c[3])
        : "r"(a[0]), "r"(a[1]), "r"(a[2]), "r"(a[3]), "r"(b0), "r"(b1));
}

// ================= bf16-split mma.sync GEMM ====================================
// C[M=TOK, N=DM] = (Ahi+Alo)[M,K] @ (Bhi+Blo)^T + bias, with B stored [N,K].
// CTA tile 128x128, K chunk 64 (128-byte SW128 rows), 3-stage cp.async pipeline.
// grid.z batches independent GEMMs (A offset z*TOK*DM, W offset z*DM*DM).
#define KC      64
#define NKC     (DM / KC)               // 8
#define TILE_B  (128 * 128)             // 16 KB per array per stage
#define STG_B   (4 * TILE_B)            // 64 KB per stage
#define NSTG    3
#define GEMM_SMEM (NSTG * STG_B)        // 196608

__global__ void __launch_bounds__(256, 1)
gemm_mma(const __nv_bfloat16* __restrict__ Ahi_base, const __nv_bfloat16* __restrict__ Alo_base,
         const __nv_bfloat16* __restrict__ Whi_base, const __nv_bfloat16* __restrict__ Wlo_base,
         GOut outs)
{
    extern __shared__ char smem[];
    const uint32_t sb = smem_u32(smem);
    const int tid  = threadIdx.x;
    const int wid  = tid >> 5;
    const int lane = tid & 31;
    const int m0   = blockIdx.y * 128;
    const int n0   = blockIdx.x * 128;
    const int z    = blockIdx.z;

    const __nv_bfloat16* arrs[4] = {
        Ahi_base + (size_t)z * TOK * DM, Alo_base + (size_t)z * TOK * DM,
        Whi_base + (size_t)z * DM * DM,  Wlo_base + (size_t)z * DM * DM };
    float* C = outs.C[z];
    const float* bias = outs.bias[z];

    // cp.async mapping: thread -> row tid/2, four 16B chunks (tid&1)*4 .. +3
    const int lrow = tid >> 1;
    const int lc0  = (tid & 1) * 4;

    auto load_stage = [&](int kc, int s) {
        const uint32_t stg = sb + s * STG_B;
        #pragma unroll
        for (int a = 0; a < 4; a++) {
            const int grow = ((a < 2) ? m0 : n0) + lrow;
            const __nv_bfloat16* src = arrs[a] + (size_t)grow * DM + kc * KC + lc0 * 8;
            const uint32_t abase = stg + a * TILE_B;
            #pragma unroll
            for (int c = 0; c < 4; c++)
                cp16(abase + sw128(lrow * 128 + (lc0 + c) * 16), src + c * 8);
        }
        asm volatile("cp.async.commit_group;" ::: "memory");
    };

    load_stage(0, 0);
    load_stage(1, 1);

    // warp tiling: warp tile 64(m) x 32(n)
    const int wm = (wid & 1) * 64;
    const int wn = (wid >> 1) * 32;
    const int lane8 = lane & 7;
    const int rowp8 = ((lane >> 3) & 1) * 8;
    const int kp1   = (lane >> 4) & 1;

    float acc[4][4][4];
    #pragma unroll
    for (int f = 0; f < 4; f++)
        #pragma unroll
        for (int n = 0; n < 4; n++)
            #pragma unroll
            for (int e = 0; e < 4; e++) acc[f][n][e] = 0.f;

    for (int kc = 0; kc < NKC; kc++) {
        const int s = kc % NSTG;
        if (kc + 2 < NKC) load_stage(kc + 2, (kc + 2) % NSTG);

        if (kc < NKC - 2)       asm volatile("cp.async.wait_group 2;" ::: "memory");
        else if (kc == NKC - 2) asm volatile("cp.async.wait_group 1;" ::: "memory");
        else                    asm volatile("cp.async.wait_group 0;" ::: "memory");
        __syncthreads();

        const uint32_t sAh = sb + s * STG_B + 0 * TILE_B;
        const uint32_t sAl = sb + s * STG_B + 1 * TILE_B;
        const uint32_t sBh = sb + s * STG_B + 2 * TILE_B;
        const uint32_t sBl = sb + s * STG_B + 3 * TILE_B;

        #pragma unroll
        for (int kk = 0; kk < KC / 16; kk++) {
            const int ch = kk * 2 + kp1;
            uint32_t bh[2][4], bl[2][4];
            #pragma unroll
            for (int p = 0; p < 2; p++) {
                const uint32_t off = sw128((wn + p * 16 + lane8 + rowp8) * 128 + ch * 16);
                ldsm4(bh[p], sBh + off);
                ldsm4(bl[p], sBl + off);
            }
            #pragma unroll
            for (int f = 0; f < 4; f++) {
                const uint32_t off = sw128((wm + f * 16 + lane8 + rowp8) * 128 + ch * 16);
                uint32_t ah[4], al[4];
                ldsm4(ah, sAh + off);
                ldsm4(al, sAl + off);
                #pragma unroll
                for (int p = 0; p < 2; p++) {
                    mma16816(acc[f][2 * p + 0], ah, bh[p][0], bh[p][2]);
                    mma16816(acc[f][2 * p + 1], ah, bh[p][1], bh[p][3]);
                    mma16816(acc[f][2 * p + 0], ah, bl[p][0], bl[p][2]);
                    mma16816(acc[f][2 * p + 1], ah, bl[p][1], bl[p][3]);
                    mma16816(acc[f][2 * p + 0], al, bh[p][0], bh[p][2]);
                    mma16816(acc[f][2 * p + 1], al, bh[p][1], bh[p][3]);
                }
            }
        }
        __syncthreads();
    }

    // epilogue
    const int row0 = m0 + wm + (lane >> 2);
    const int colb = n0 + wn + (lane & 3) * 2;
    #pragma unroll
    for (int f = 0; f < 4; f++) {
        #pragma unroll
        for (int n = 0; n < 4; n++) {
            const int col = colb + n * 8;
            const float2 bv = *(const float2*)(bias + col);
            float2 o0, o1;
            o0.x = acc[f][n][0] + bv.x; o0.y = acc[f][n][1] + bv.y;
            o1.x = acc[f][n][2] + bv.x; o1.y = acc[f][n][3] + bv.y;
            *(float2*)(C + (size_t)(row0 + f * 16 + 0) * DM + col) = o0;
            *(float2*)(C + (size_t)(row0 + f * 16 + 8) * DM + col) = o1;
        }
    }
}

// ================= conversion kernels ==========================================
// fp32 -> (hi, lo) bf16 split; grid.y selects source, output offset y*TOK*DM/4
__global__ void conv_act(CIn in, __nv_bfloat16* __restrict__ hi, __nv_bfloat16* __restrict__ lo)
{
    const int z = blockIdx.y;
    const size_t i = (size_t)blockIdx.x * blockDim.x + threadIdx.x;   // over float4s
    const size_t o = (size_t)z * (TOK * DM / 4) + i;
    float4 v = ((const float4*)in.x[z])[i];
    __nv_bfloat16 h[4], l[4];
    float f[4] = { v.x, v.y, v.z, v.w };
    #pragma unroll
    for (int t = 0; t < 4; t++) {
        h[t] = __float2bfloat16_rn(f[t]);
        l[t] = __float2bfloat16_rn(f[t] - __bfloat162float(h[t]));
    }
    ((ushort4*)hi)[o] = make_ushort4(__bfloat16_as_ushort(h[0]), __bfloat16_as_ushort(h[1]),
                                     __bfloat16_as_ushort(h[2]), __bfloat16_as_ushort(h[3]));
    ((ushort4*)lo)[o] = make_ushort4(__bfloat16_as_ushort(l[0]), __bfloat16_as_ushort(l[1]),
                                     __bfloat16_as_ushort(l[2]), __bfloat16_as_ushort(l[3]));
}

// W [K,N] fp32 row-major -> Wt [N,K] bf16 hi/lo (transposed); grid.z selects weight
__global__ void wt_all(WIn in, __nv_bfloat16* __restrict__ hi, __nv_bfloat16* __restrict__ lo)
{
    __shared__ float t[32][33];
    const int z = blockIdx.z;
    const float* W = in.W[z];
    __nv_bfloat16* ho = hi + (size_t)z * DM * DM;
    __nv_bfloat16* lo2 = lo + (size_t)z * DM * DM;
    const int bx = blockIdx.x * 32;   // n
    const int by = blockIdx.y * 32;   // k
    const int x = threadIdx.x, y = threadIdx.y;
    #pragma unroll
    for (int r = y; r < 32; r += 8)
        t[r][x] = W[(size_t)(by + r) * DM + bx + x];
    __syncthreads();
    #pragma unroll
    for (int i = y; i < 32; i += 8) {
        float v = t[x][i];
        __nv_bfloat16 h = __float2bfloat16_rn(v);
        __nv_bfloat16 l = __float2bfloat16_rn(v - __bfloat162float(h));
        size_t o = (size_t)(bx + i) * DM + by + x;
        ho[o] = h;
        lo2[o] = l;
    }
}

// ================= V column-sum ================================================
__global__ void vsum_part(const float* __restrict__ V)
{
    int b = blockIdx.y, chunk = blockIdx.x, c = threadIdx.x;
    const int rows = SEQ / VCHUNK;
    const float* p = V + ((size_t)b * SEQ + (size_t)chunk * rows) * DM + c;
    float s = 0.f;
    #pragma unroll 4
    for (int r = 0; r < rows; r++) s += p[(size_t)r * DM];
    g_vpart[chunk][b * DM + c] = s;
}

__global__ void vsum_final()
{
    int idx = blockIdx.x * blockDim.x + threadIdx.x;
    if (idx >= BS * DM) return;
    float s = 0.f;
    #pragma unroll
    for (int t = 0; t < VCHUNK; t++) s += g_vpart[t][idx];
    g_vsum[idx] = s;
}

// ================= banded attention (closed-form full-row softmax) ==============
__global__ __launch_bounds__(256)
void attn_kernel(const float* __restrict__ Q, const float* __restrict__ K,
                 const float* __restrict__ V, float* __restrict__ ctx)
{
    int gwarp = (blockIdx.x * blockDim.x + threadIdx.x) >> 5;
    int lane  = threadIdx.x & 31;

    int i  = gwarp % SEQ;
    int bh = gwarp / SEQ;
    int h  = bh % HEADS;
    int b  = bh / HEADS;

    const size_t base = ((size_t)b * SEQ) * DM + h * DK + 2 * lane;
    float2 qv = *(const float2*)(Q + base + (size_t)i * DM);

    int jlo = i - 4; if (jlo < 0) jlo = 0;
    int jhi = i + 4; if (jhi > SEQ - 1) jhi = SEQ - 1;
    int nb = jhi - jlo + 1;

    float s[9];
    float smax = 0.f;
    #pragma unroll
    for (int t = 0; t < 9; t++) {
        int j = jlo + t;
        bool valid = (j <= jhi);
        int jc = valid ? j : jhi;
        float2 kv = *(const float2*)(K + base + (size_t)jc * DM);
        float p = qv.x * kv.x + qv.y * kv.y;
        #pragma unroll
        for (int o = 16; o; o >>= 1) p += __shfl_xor_sync(0xffffffffu, p, o);
        int mn = min(i, j), mx = max(i, j);
        int clo = mx - 2; if (clo < 0) clo = 0;
        int chi = mn + 2; if (chi > SEQ - 1) chi = SEQ - 1;
        float cc = (float)(chi - clo + 1);
        s[t] = valid ? p * 0.125f * cc : -1e30f;
        smax = fmaxf(smax, s[t]);
    }

    float w0 = expf(-smax);
    float Z  = (float)(SEQ - nb) * w0;
    float w[9];
    #pragma unroll
    for (int t = 0; t < 9; t++) { w[t] = expf(s[t] - smax); Z += w[t]; }
    float rZ = 1.f / Z;

    float2 acc; acc.x = 0.f; acc.y = 0.f;
    #pragma unroll
    for (int t = 0; t < 9; t++) {
        int j = jlo + t;
        bool valid = (j <= jhi);
        int jc = valid ? j : jhi;
        float2 vv = *(const float2*)(V + base + (size_t)jc * DM);
        float wt = valid ? (w[t] - w0) : 0.f;
        acc.x += wt * vv.x;
        acc.y += wt * vv.y;
    }
    float2 vs = *(const float2*)(g_vsum + b * DM + h * DK + 2 * lane);
    acc.x = (acc.x + w0 * vs.x) * rZ;
    acc.y = (acc.y + w0 * vs.y) * rZ;

    *(float2*)(ctx + base + (size_t)i * DM) = acc;
}

// ================= launch =======================================================
extern "C" void kernel_launch(void* const* d_in, const int* in_sizes, int n_in,
                              void* d_out, int out_size)
{
    const float* q  = (const float*)d_in[0];
    const float* k  = (const float*)d_in[1];
    const float* v  = (const float*)d_in[2];
    const float* Wq = (const float*)d_in[3];
    const float* bq = (const float*)d_in[4];
    const float* Wk = (const float*)d_in[5];
    const float* bk = (const float*)d_in[6];
    const float* Wv = (const float*)d_in[7];
    const float* bv = (const float*)d_in[8];
    const float* Wo = (const float*)d_in[9];
    const float* bo = (const float*)d_in[10];
    float* out = (float*)d_out;

    float *pQ, *pK, *pV, *pCtx;
    __nv_bfloat16 *pAhi, *pAlo, *pWhi, *pWlo;
    cudaGetSymbolAddress((void**)&pQ,   g_Q);
    cudaGetSymbolAddress((void**)&pK,   g_K);
    cudaGetSymbolAddress((void**)&pV,   g_V);
    cudaGetSymbolAddress((void**)&pCtx, g_ctx);
    cudaGetSymbolAddress((void**)&pAhi, g_ahi);
    cudaGetSymbolAddress((void**)&pAlo, g_alo);
    cudaGetSymbolAddress((void**)&pWhi, g_wthi);
    cudaGetSymbolAddress((void**)&pWlo, g_wtlo);

    cudaFuncSetAttribute(gemm_mma, cudaFuncAttributeMaxDynamicSharedMemorySize, GEMM_SMEM);

    // weight transpose + bf16 split: all 4 weights in one launch
    WIn win; win.W[0] = Wq; win.W[1] = Wk; win.W[2] = Wv; win.W[3] = Wo;
    wt_all<<<dim3(DM / 32, DM / 32, 4), dim3(32, 8)>>>(win, pWhi, pWlo);

    const int CVB = 256, CVG = (TOK * DM / 4) / CVB;

    // convert q,k,v in one launch
    CIn cin; cin.x[0] = q; cin.x[1] = k; cin.x[2] = v;
    conv_act<<<dim3(CVG, 3), CVB>>>(cin, pAhi, pAlo);

    // Q,K,V projections in one batched launch (384 CTAs)
    GOut g3;
    g3.C[0] = pQ;  g3.C[1] = pK;  g3.C[2] = pV;
    g3.bias[0] = bq; g3.bias[1] = bk; g3.bias[2] = bv;
    gemm_mma<<<dim3(DM / 128, TOK / 128, 3), 256, GEMM_SMEM>>>(pAhi, pAlo, pWhi, pWlo, g3);

    // attention
    vsum_part<<<dim3(VCHUNK, BS), DM>>>(pV);
    vsum_final<<<(BS * DM + 255) / 256, 256>>>();
    int warps = BS * HEADS * SEQ;
    attn_kernel<<<warps / 8, 256>>>(pQ, pK, pV, pCtx);

    // out = ctx@Wo+bo
    CIn cctx; cctx.x[0] = pCtx; cctx.x[1] = pCtx; cctx.x[2] = pCtx;
    conv_act<<<dim3(CVG, 1), CVB>>>(cctx, pAhi, pAlo);
    GOut g1;
    g1.C[0] = out; g1.C[1] = out; g1.C[2] = out;
    g1.bias[0] = bo; g1.bias[1] = bo; g1.bias[2] = bo;
    gemm_mma<<<dim3(DM / 128, TOK / 128, 1), 256, GEMM_SMEM>>>(
        pAhi, pAlo, pWhi + 3 * (size_t)DM * DM, pWlo + 3 * (size_t)DM * DM, g1);
}

// round 8
// speedup vs baseline: 1.1003x; 1.1003x over previous
#include <cuda_runtime.h>
#include <cuda_bf16.h>
#include <math.h>
#include <stdint.h>

// Problem constants: bs=2, seq=2048, d_model=512, heads=8, d_k=64
#define DM     512
#define HEADS  8
#define DK     64
#define SEQ    2048
#define BS     2
#define TOK    (SEQ*BS)     // 4096

// ---------------- scratch (device globals; no allocations allowed) -------------
__device__ float g_Q[TOK * DM];
__device__ float g_K[TOK * DM];
__device__ float g_V[TOK * DM];
__device__ __nv_bfloat16 g_ahi[3 * TOK * DM];
__device__ __nv_bfloat16 g_alo[3 * TOK * DM];
__device__ __nv_bfloat16 g_wthi[4][DM * DM];   // transposed weights [N,K], hi part
__device__ __nv_bfloat16 g_wtlo[4][DM * DM];   // lo part
__device__ float g_vsum[BS * DM];

struct WIn  { const float* W[4]; };
struct CIn  { const float* x[3]; };
struct GOut { float* C[3]; const float* bias[3]; };

// ================= helpers ======================================================
__device__ __forceinline__ uint32_t smem_u32(const void* p) {
    uint32_t a;
    asm("{ .reg .u64 t; cvta.to.shared.u64 t, %1; cvt.u32.u64 %0, t; }" : "=r"(a) : "l"(p));
    return a;
}
__device__ __forceinline__ uint32_t sw128(uint32_t o) { return o ^ ((o >> 3) & 0x70); }

__device__ __forceinline__ void cp16(uint32_t dst, const void* src) {
    asm volatile("cp.async.cg.shared.global [%0], [%1], 16;" :: "r"(dst), "l"(src));
}
__device__ __forceinline__ void ldsm4(uint32_t* r, uint32_t addr) {
    asm volatile("ldmatrix.sync.aligned.m8n8.x4.shared.b16 {%0,%1,%2,%3}, [%4];"
        : "=r"(r[0]), "=r"(r[1]), "=r"(r[2]), "=r"(r[3]) : "r"(addr));
}
__device__ __forceinline__ void mma16816(float* c, const uint32_t* a, uint32_t b0, uint32_t b1) {
    asm volatile("mma.sync.aligned.m16n8k16.row.col.f32.bf16.bf16.f32 "
        "{%0,%1,%2,%3}, {%4,%5,%6,%7}, {%8,%9}, {%0,%1,%2,%3};"
        : "+f"(c[0]), "+f"(c[1]), "+f"(c[2]), "+f"(c[3])
        : "r"(a[0]), "r"(a[1]), "r"(a[2]), "r"(a[3]), "r"(b0), "r"(b1));
}

// ================= bf16-split mma.sync GEMM ====================================
// C[M=TOK, N=DM] = (Ahi+Alo)[M,K] @ (Bhi+Blo)^T + bias, with B stored [N,K].
// CTA tile 128x128, K chunk 64 (128-byte SW128 rows), 2-stage cp.async pipeline.
// grid.z batches independent GEMMs. z == vsum_z additionally accumulates the
// per-batch column sums of its output tile into g_vsum (post-bias).
#define KC      64
#define NKC     (DM / KC)               // 8
#define TILE_B  (128 * 128)             // 16 KB per array per stage
#define STG_B   (4 * TILE_B)            // 64 KB per stage
#define GEMM_SMEM (2 * STG_B)           // 131072

__global__ void __launch_bounds__(256, 1)
gemm_mma(const __nv_bfloat16* __restrict__ Ahi_base, const __nv_bfloat16* __restrict__ Alo_base,
         const __nv_bfloat16* __restrict__ Whi_base, const __nv_bfloat16* __restrict__ Wlo_base,
         GOut outs, int vsum_z)
{
    extern __shared__ char smem[];
    const uint32_t sb = smem_u32(smem);
    const int tid  = threadIdx.x;
    const int wid  = tid >> 5;
    const int lane = tid & 31;
    const int m0   = blockIdx.y * 128;
    const int n0   = blockIdx.x * 128;
    const int z    = blockIdx.z;

    const __nv_bfloat16* arrs[4] = {
        Ahi_base + (size_t)z * TOK * DM, Alo_base + (size_t)z * TOK * DM,
        Whi_base + (size_t)z * DM * DM,  Wlo_base + (size_t)z * DM * DM };
    float* C = outs.C[z];
    const float* bias = outs.bias[z];

    // cp.async mapping: thread -> row tid/2, four 16B chunks (tid&1)*4 .. +3
    const int lrow = tid >> 1;
    const int lc0  = (tid & 1) * 4;

    auto load_stage = [&](int kc, int s) {
        const uint32_t stg = sb + s * STG_B;
        #pragma unroll
        for (int a = 0; a < 4; a++) {
            const int grow = ((a < 2) ? m0 : n0) + lrow;
            const __nv_bfloat16* src = arrs[a] + (size_t)grow * DM + kc * KC + lc0 * 8;
            const uint32_t abase = stg + a * TILE_B;
            #pragma unroll
            for (int c = 0; c < 4; c++)
                cp16(abase + sw128(lrow * 128 + (lc0 + c) * 16), src + c * 8);
        }
        asm volatile("cp.async.commit_group;" ::: "memory");
    };

    load_stage(0, 0);
    load_stage(1, 1);

    // warp tiling: warp tile 64(m) x 32(n)
    const int wm = (wid & 1) * 64;
    const int wn = (wid >> 1) * 32;
    const int lane8 = lane & 7;
    const int rowp8 = ((lane >> 3) & 1) * 8;
    const int kp1   = (lane >> 4) & 1;

    float acc[4][4][4];
    #pragma unroll
    for (int f = 0; f < 4; f++)
        #pragma unroll
        for (int n = 0; n < 4; n++)
            #pragma unroll
            for (int e = 0; e < 4; e++) acc[f][n][e] = 0.f;

    for (int kc = 0; kc < NKC; kc++) {
        const int s = kc & 1;
        if (kc < NKC - 1) asm volatile("cp.async.wait_group 1;" ::: "memory");
        else              asm volatile("cp.async.wait_group 0;" ::: "memory");
        __syncthreads();

        const uint32_t sAh = sb + s * STG_B + 0 * TILE_B;
        const uint32_t sAl = sb + s * STG_B + 1 * TILE_B;
        const uint32_t sBh = sb + s * STG_B + 2 * TILE_B;
        const uint32_t sBl = sb + s * STG_B + 3 * TILE_B;

        #pragma unroll
        for (int kk = 0; kk < KC / 16; kk++) {
            const int ch = kk * 2 + kp1;
            // hoist all fragment loads for this k-step
            uint32_t bh[2][4], bl[2][4];
            #pragma unroll
            for (int p = 0; p < 2; p++) {
                const uint32_t off = sw128((wn + p * 16 + lane8 + rowp8) * 128 + ch * 16);
                ldsm4(bh[p], sBh + off);
                ldsm4(bl[p], sBl + off);
            }
            uint32_t ah[4][4], al[4][4];
            #pragma unroll
            for (int f = 0; f < 4; f++) {
                const uint32_t off = sw128((wm + f * 16 + lane8 + rowp8) * 128 + ch * 16);
                ldsm4(ah[f], sAh + off);
                ldsm4(al[f], sAl + off);
            }
            #pragma unroll
            for (int f = 0; f < 4; f++) {
                #pragma unroll
                for (int p = 0; p < 2; p++) {
                    mma16816(acc[f][2 * p + 0], ah[f], bh[p][0], bh[p][2]);
                    mma16816(acc[f][2 * p + 1], ah[f], bh[p][1], bh[p][3]);
                    mma16816(acc[f][2 * p + 0], ah[f], bl[p][0], bl[p][2]);
                    mma16816(acc[f][2 * p + 1], ah[f], bl[p][1], bl[p][3]);
                    mma16816(acc[f][2 * p + 0], al[f], bh[p][0], bh[p][2]);
                    mma16816(acc[f][2 * p + 1], al[f], bh[p][1], bh[p][3]);
                }
            }
        }
        __syncthreads();
        if (kc + 2 < NKC) load_stage(kc + 2, s);
    }

    // epilogue (post-bias values), optional fused column-sum for V
    const int row0 = m0 + wm + (lane >> 2);
    const int colb = n0 + wn + (lane & 3) * 2;
    float cs0[4], cs1[4];   // per-thread column partial sums (post-bias)
    #pragma unroll
    for (int n = 0; n < 4; n++) { cs0[n] = 0.f; cs1[n] = 0.f; }

    #pragma unroll
    for (int f = 0; f < 4; f++) {
        #pragma unroll
        for (int n = 0; n < 4; n++) {
            const int col = colb + n * 8;
            const float2 bv = *(const float2*)(bias + col);
            float2 o0, o1;
            o0.x = acc[f][n][0] + bv.x; o0.y = acc[f][n][1] + bv.y;
            o1.x = acc[f][n][2] + bv.x; o1.y = acc[f][n][3] + bv.y;
            cs0[n] += o0.x + o1.x;
            cs1[n] += o0.y + o1.y;
            *(float2*)(C + (size_t)(row0 + f * 16 + 0) * DM + col) = o0;
            *(float2*)(C + (size_t)(row0 + f * 16 + 8) * DM + col) = o1;
        }
    }

    if (z == vsum_z) {
        // reduce across the 8 lanes that share (lane & 3): xor lane bits 2,3,4
        #pragma unroll
        for (int n = 0; n < 4; n++) {
            #pragma unroll
            for (int o = 4; o <= 16; o <<= 1) {
                cs0[n] += __shfl_xor_sync(0xffffffffu, cs0[n], o);
                cs1[n] += __shfl_xor_sync(0xffffffffu, cs1[n], o);
            }
        }
        if (lane < 4) {
            const int b = m0 / SEQ;
            #pragma unroll
            for (int n = 0; n < 4; n++) {
                const int col = n0 + wn + (lane & 3) * 2 + n * 8;
                atomicAdd(&g_vsum[b * DM + col + 0], cs0[n]);
                atomicAdd(&g_vsum[b * DM + col + 1], cs1[n]);
            }
        }
    }
}

// ================= conversion kernels ==========================================
// fp32 -> (hi, lo) bf16 split; grid.y selects source, output offset y*TOK*DM/4
__global__ void conv_act(CIn in, __nv_bfloat16* __restrict__ hi, __nv_bfloat16* __restrict__ lo)
{
    const int z = blockIdx.y;
    const size_t i = (size_t)blockIdx.x * blockDim.x + threadIdx.x;   // over float4s
    const size_t o = (size_t)z * (TOK * DM / 4) + i;
    float4 v = ((const float4*)in.x[z])[i];
    __nv_bfloat16 h[4], l[4];
    float f[4] = { v.x, v.y, v.z, v.w };
    #pragma unroll
    for (int t = 0; t < 4; t++) {
        h[t] = __float2bfloat16_rn(f[t]);
        l[t] = __float2bfloat16_rn(f[t] - __bfloat162float(h[t]));
    }
    ((ushort4*)hi)[o] = make_ushort4(__bfloat16_as_ushort(h[0]), __bfloat16_as_ushort(h[1]),
                                     __bfloat16_as_ushort(h[2]), __bfloat16_as_ushort(h[3]));
    ((ushort4*)lo)[o] = make_ushort4(__bfloat16_as_ushort(l[0]), __bfloat16_as_ushort(l[1]),
                                     __bfloat16_as_ushort(l[2]), __bfloat16_as_ushort(l[3]));
}

// W [K,N] fp32 row-major -> Wt [N,K] bf16 hi/lo (transposed); grid.z selects weight.
// Block (0,0,0) also zeroes g_vsum for the fused V column-sum.
__global__ void wt_all(WIn in, __nv_bfloat16* __restrict__ hi, __nv_bfloat16* __restrict__ lo)
{
    __shared__ float t[32][33];
    const int z = blockIdx.z;
    const float* W = in.W[z];
    __nv_bfloat16* ho = hi + (size_t)z * DM * DM;
    __nv_bfloat16* lo2 = lo + (size_t)z * DM * DM;
    const int bx = blockIdx.x * 32;   // n
    const int by = blockIdx.y * 32;   // k
    const int x = threadIdx.x, y = threadIdx.y;
    const int tid = y * 32 + x;

    if (z == 0 && blockIdx.x == 0 && blockIdx.y == 0) {
        #pragma unroll
        for (int r = 0; r < BS * DM / 256; r++) g_vsum[tid + r * 256] = 0.f;
    }

    #pragma unroll
    for (int r = y; r < 32; r += 8)
        t[r][x] = W[(size_t)(by + r) * DM + bx + x];
    __syncthreads();
    #pragma unroll
    for (int i = y; i < 32; i += 8) {
        float v = t[x][i];
        __nv_bfloat16 h = __float2bfloat16_rn(v);
        __nv_bfloat16 l = __float2bfloat16_rn(v - __bfloat162float(h));
        size_t o = (size_t)(bx + i) * DM + by + x;
        ho[o] = h;
        lo2[o] = l;
    }
}

// ================= banded attention (closed-form full-row softmax) ==============
// Writes ctx directly as bf16 hi/lo into the GEMM activation buffers (slot 0).
__global__ __launch_bounds__(256)
void attn_kernel(const float* __restrict__ Q, const float* __restrict__ K,
                 const float* __restrict__ V,
                 __nv_bfloat16* __restrict__ chi, __nv_bfloat16* __restrict__ clo)
{
    int gwarp = (blockIdx.x * blockDim.x + threadIdx.x) >> 5;
    int lane  = threadIdx.x & 31;

    int i  = gwarp % SEQ;
    int bh = gwarp / SEQ;
    int h  = bh % HEADS;
    int b  = bh / HEADS;

    const size_t base = ((size_t)b * SEQ) * DM + h * DK + 2 * lane;
    float2 qv = *(const float2*)(Q + base + (size_t)i * DM);

    int jlo = i - 4; if (jlo < 0) jlo = 0;
    int jhi = i + 4; if (jhi > SEQ - 1) jhi = SEQ - 1;
    int nb = jhi - jlo + 1;

    float s[9];
    float smax = 0.f;
    #pragma unroll
    for (int t = 0; t < 9; t++) {
        int j = jlo + t;
        bool valid = (j <= jhi);
        int jc = valid ? j : jhi;
        float2 kv = *(const float2*)(K + base + (size_t)jc * DM);
        float p = qv.x * kv.x + qv.y * kv.y;
        #pragma unroll
        for (int o = 16; o; o >>= 1) p += __shfl_xor_sync(0xffffffffu, p, o);
        int mn = min(i, j), mx = max(i, j);
        int clo2 = mx - 2; if (clo2 < 0) clo2 = 0;
        int chi2 = mn + 2; if (chi2 > SEQ - 1) chi2 = SEQ - 1;
        float cc = (float)(chi2 - clo2 + 1);
        s[t] = valid ? p * 0.125f * cc : -1e30f;
        smax = fmaxf(smax, s[t]);
    }

    float w0 = expf(-smax);
    float Z  = (float)(SEQ - nb) * w0;
    float w[9];
    #pragma unroll
    for (int t = 0; t < 9; t++) { w[t] = expf(s[t] - smax); Z += w[t]; }
    float rZ = 1.f / Z;

    float2 acc; acc.x = 0.f; acc.y = 0.f;
    #pragma unroll
    for (int t = 0; t < 9; t++) {
        int j = jlo + t;
        bool valid = (j <= jhi);
        int jc = valid ? j : jhi;
        float2 vv = *(const float2*)(V + base + (size_t)jc * DM);
        float wt = valid ? (w[t] - w0) : 0.f;
        acc.x += wt * vv.x;
        acc.y += wt * vv.y;
    }
    float2 vs = *(const float2*)(g_vsum + b * DM + h * DK + 2 * lane);
    acc.x = (acc.x + w0 * vs.x) * rZ;
    acc.y = (acc.y + w0 * vs.y) * rZ;

    // bf16 hi/lo split, written directly to the GEMM input buffers
    __nv_bfloat16 hx = __float2bfloat16_rn(acc.x);
    __nv_bfloat16 hy = __float2bfloat16_rn(acc.y);
    __nv_bfloat16 lx = __float2bfloat16_rn(acc.x - __bfloat162float(hx));
    __nv_bfloat16 ly = __float2bfloat16_rn(acc.y - __bfloat162float(hy));
    const size_t o = base + (size_t)i * DM;
    *(ushort2*)(chi + o) = make_ushort2(__bfloat16_as_ushort(hx), __bfloat16_as_ushort(hy));
    *(ushort2*)(clo + o) = make_ushort2(__bfloat16_as_ushort(lx), __bfloat16_as_ushort(ly));
}

// ================= launch =======================================================
extern "C" void kernel_launch(void* const* d_in, const int* in_sizes, int n_in,
                              void* d_out, int out_size)
{
    const float* q  = (const float*)d_in[0];
    const float* k  = (const float*)d_in[1];
    const float* v  = (const float*)d_in[2];
    const float* Wq = (const float*)d_in[3];
    const float* bq = (const float*)d_in[4];
    const float* Wk = (const float*)d_in[5];
    const float* bk = (const float*)d_in[6];
    const float* Wv = (const float*)d_in[7];
    const float* bv = (const float*)d_in[8];
    const float* Wo = (const float*)d_in[9];
    const float* bo = (const float*)d_in[10];
    float* out = (float*)d_out;

    float *pQ, *pK, *pV;
    __nv_bfloat16 *pAhi, *pAlo, *pWhi, *pWlo;
    cudaGetSymbolAddress((void**)&pQ,   g_Q);
    cudaGetSymbolAddress((void**)&pK,   g_K);
    cudaGetSymbolAddress((void**)&pV,   g_V);
    cudaGetSymbolAddress((void**)&pAhi, g_ahi);
    cudaGetSymbolAddress((void**)&pAlo, g_alo);
    cudaGetSymbolAddress((void**)&pWhi, g_wthi);
    cudaGetSymbolAddress((void**)&pWlo, g_wtlo);

    cudaFuncSetAttribute(gemm_mma, cudaFuncAttributeMaxDynamicSharedMemorySize, GEMM_SMEM);

    // weight transpose + bf16 split (also zeroes g_vsum)
    WIn win; win.W[0] = Wq; win.W[1] = Wk; win.W[2] = Wv; win.W[3] = Wo;
    wt_all<<<dim3(DM / 32, DM / 32, 4), dim3(32, 8)>>>(win, pWhi, pWlo);

    const int CVB = 256, CVG = (TOK * DM / 4) / CVB;

    // convert q,k,v in one launch
    CIn cin; cin.x[0] = q; cin.x[1] = k; cin.x[2] = v;
    conv_act<<<dim3(CVG, 3), CVB>>>(cin, pAhi, pAlo);

    // Q,K,V projections in one batched launch; V (z=2) fuses column-sum
    GOut g3;
    g3.C[0] = pQ;  g3.C[1] = pK;  g3.C[2] = pV;
    g3.bias[0] = bq; g3.bias[1] = bk; g3.bias[2] = bv;
    gemm_mma<<<dim3(DM / 128, TOK / 128, 3), 256, GEMM_SMEM>>>(pAhi, pAlo, pWhi, pWlo, g3, 2);

    // attention -> ctx written as bf16 hi/lo into activation slot 0
    int warps = BS * HEADS * SEQ;
    attn_kernel<<<warps / 8, 256>>>(pQ, pK, pV, pAhi, pAlo);

    // out = ctx@Wo+bo
    GOut g1;
    g1.C[0] = out; g1.C[1] = out; g1.C[2] = out;
    g1.bias[0] = bo; g1.bias[1] = bo; g1.bias[2] = bo;
    gemm_mma<<<dim3(DM / 128, TOK / 128, 1), 256, GEMM_SMEM>>>(
        pAhi, pAlo, pWhi + 3 * (size_t)DM * DM, pWlo + 3 * (size_t)DM * DM, g1, -1);
}